// round 6
// baseline (speedup 1.0000x reference)
#include <cuda_runtime.h>
#include <cuda_fp16.h>

#define N_NODES  50000
#define IN_DIM   128
#define N_HEADS  8
#define OUT_DIM  16
#define HD       (N_HEADS * OUT_DIM)   // 128
#define MAX_EDGES 1600000

// -------- scratch (static device globals; allocation-free) --------
__device__ __align__(16) __half g_Qh [(size_t)N_NODES * HD];
// interleaved K|V: per node 32 groups x (4 K halves + 4 V halves) = 256 halves
__device__ __align__(16) __half g_KVh[(size_t)N_NODES * 2 * HD];
__device__ int g_hist[N_NODES];
__device__ int g_rowptr[N_NODES + 1];
__device__ int g_cursor[N_NODES];
__device__ int g_srcsorted[MAX_EDGES];

// ---- packed f32x2 helpers (Blackwell: 2x fp32 FMA per instruction) ----
#define PACK2(p, lo, hi) \
    asm("mov.b64 %0, {%1, %2};" : "=l"(p) : "f"(lo), "f"(hi))
#define UNPACK2(lo, hi, p) \
    asm("mov.b64 {%0, %1}, %2;" : "=f"(lo), "=f"(hi) : "l"(p))
#define FMA2(d, a, b) \
    asm("fma.rn.f32x2 %0, %1, %2, %0;" : "+l"(d) : "l"(a), "l"(b))

// =================================================================
// CSR build: histogram -> scan -> scatter (counting sort by dst)
// =================================================================
__global__ void hist_kernel(const int* __restrict__ dst, int n_edges)
{
    int e = blockIdx.x * blockDim.x + threadIdx.x;
    if (e < n_edges) atomicAdd(&g_hist[dst[e]], 1);
}

// single block, 1024 threads; 50000 entries, 49 per thread
__global__ __launch_bounds__(1024) void scan_kernel()
{
    __shared__ int part[1024];
    const int CHUNK = 49;
    int t = threadIdx.x;
    int begin = t * CHUNK;
    int end   = begin + CHUNK; if (end > N_NODES) end = N_NODES;
    if (begin > N_NODES) begin = N_NODES;

    int s = 0;
    for (int i = begin; i < end; i++) s += g_hist[i];
    part[t] = s;
    __syncthreads();

    for (int off = 1; off < 1024; off <<= 1) {
        int v = (t >= off) ? part[t - off] : 0;
        __syncthreads();
        part[t] += v;
        __syncthreads();
    }

    int base = (t == 0) ? 0 : part[t - 1];
    for (int i = begin; i < end; i++) {
        g_rowptr[i] = base;
        g_cursor[i] = base;
        base += g_hist[i];
    }
    if (t == 1023) g_rowptr[N_NODES] = part[1023];
}

__global__ void scatter_kernel(const int* __restrict__ src,
                               const int* __restrict__ dst, int n_edges)
{
    int e = blockIdx.x * blockDim.x + threadIdx.x;
    if (e < n_edges) {
        int d = dst[e];
        int pos = atomicAdd(&g_cursor[d], 1);
        g_srcsorted[pos] = src[e];
    }
}

// =================================================================
// QKV projection: out = state @ W + b, one of Q/K/V per blockIdx.z.
// BM=128, BN=128(=HD), BK=32, 256 threads, 8x8 per-thread tile,
// packed f32x2 FMAs. Q -> g_Qh; K,V -> interleaved g_KVh (fp16).
// =================================================================
__global__ __launch_bounds__(256) void qkv_gemm(
    const float* __restrict__ state,
    const float* __restrict__ WQ, const float* __restrict__ bQ,
    const float* __restrict__ WK, const float* __restrict__ bK,
    const float* __restrict__ WV, const float* __restrict__ bV)
{
    const float* W;
    const float* b;
    if (blockIdx.z == 0)      { W = WQ; b = bQ; }
    else if (blockIdx.z == 1) { W = WK; b = bK; }
    else                      { W = WV; b = bV; }

    __shared__ __align__(16) float As[32][132];   // As[k][m], 528B row stride
    __shared__ __align__(16) float Bs[32][128];   // Bs[k][n]

    const int row0 = blockIdx.x * 128;
    const int tid  = threadIdx.x;
    const int tx   = tid & 15;     // n = tx*8
    const int ty   = tid >> 4;     // m = ty*8

    unsigned long long acc[8][4];
#pragma unroll
    for (int i = 0; i < 8; i++)
#pragma unroll
        for (int p = 0; p < 4; p++) acc[i][p] = 0ULL;

    for (int k0 = 0; k0 < IN_DIM; k0 += 32) {
#pragma unroll
        for (int i = 0; i < 4; i++) {
            int idx = tid + i * 256;       // 0..1023
            int r   = idx >> 3;            // row in tile (0..127)
            int kq  = idx & 7;             // float4 index along k
            int grow = row0 + r;
            float4 a = make_float4(0.f, 0.f, 0.f, 0.f);
            if (grow < N_NODES)
                a = *reinterpret_cast<const float4*>(&state[(size_t)grow * IN_DIM + k0 + kq * 4]);
            As[kq * 4 + 0][r] = a.x;
            As[kq * 4 + 1][r] = a.y;
            As[kq * 4 + 2][r] = a.z;
            As[kq * 4 + 3][r] = a.w;
        }
#pragma unroll
        for (int i = 0; i < 4; i++) {
            int idx = tid + i * 256;
            int k   = idx >> 5;            // 0..31
            int nq  = idx & 31;            // float4 along n
            float4 wv = *reinterpret_cast<const float4*>(&W[(size_t)(k0 + k) * HD + nq * 4]);
            *reinterpret_cast<float4*>(&Bs[k][nq * 4]) = wv;
        }
        __syncthreads();

#pragma unroll
        for (int k = 0; k < 32; k++) {
            float4 a0 = *reinterpret_cast<const float4*>(&As[k][ty * 8]);
            float4 a1 = *reinterpret_cast<const float4*>(&As[k][ty * 8 + 4]);
            float4 b0 = *reinterpret_cast<const float4*>(&Bs[k][tx * 8]);
            float4 b1 = *reinterpret_cast<const float4*>(&Bs[k][tx * 8 + 4]);

            unsigned long long bp[4];
            PACK2(bp[0], b0.x, b0.y);
            PACK2(bp[1], b0.z, b0.w);
            PACK2(bp[2], b1.x, b1.y);
            PACK2(bp[3], b1.z, b1.w);

            float av[8] = { a0.x, a0.y, a0.z, a0.w, a1.x, a1.y, a1.z, a1.w };
#pragma unroll
            for (int i = 0; i < 8; i++) {
                unsigned long long ap;
                PACK2(ap, av[i], av[i]);
#pragma unroll
                for (int p = 0; p < 4; p++)
                    FMA2(acc[i][p], ap, bp[p]);
            }
        }
        __syncthreads();
    }

    float bias[8];
#pragma unroll
    for (int j = 0; j < 8; j++) bias[j] = b[tx * 8 + j];

#pragma unroll
    for (int i = 0; i < 8; i++) {
        int row = row0 + ty * 8 + i;
        if (row >= N_NODES) continue;
        float o[8];
#pragma unroll
        for (int p = 0; p < 4; p++) {
            float lo, hi;
            UNPACK2(lo, hi, acc[i][p]);
            o[2 * p]     = lo + bias[2 * p];
            o[2 * p + 1] = hi + bias[2 * p + 1];
        }
        __half2 h[4];
#pragma unroll
        for (int j = 0; j < 4; j++)
            h[j] = __floats2half2_rn(o[2 * j], o[2 * j + 1]);

        if (blockIdx.z == 0) {
            *reinterpret_cast<uint4*>(&g_Qh[(size_t)row * HD + tx * 8]) =
                *reinterpret_cast<const uint4*>(h);
        } else {
            // interleaved KV: group g (=dims 4g..4g+3) occupies halves
            // [g*8, g*8+4) for K and [g*8+4, g*8+8) for V.
            __half* rowp = &g_KVh[(size_t)row * 2 * HD];
            int off = (blockIdx.z == 1) ? 0 : 4;
            uint2 lo = make_uint2(*reinterpret_cast<unsigned*>(&h[0]),
                                  *reinterpret_cast<unsigned*>(&h[1]));
            uint2 hi = make_uint2(*reinterpret_cast<unsigned*>(&h[2]),
                                  *reinterpret_cast<unsigned*>(&h[3]));
            *reinterpret_cast<uint2*>(&rowp[(2 * tx) * 8 + off])     = lo;
            *reinterpret_cast<uint2*>(&rowp[(2 * tx + 1) * 8 + off]) = hi;
        }
    }
}

// =================================================================
// Aggregate: warp per dst node. lane l owns dims [4l,4l+4);
// head h = l>>2. Q register-resident; per edge ONE uint4 gather
// (K+V interleaved). Register accumulation, fused normalize.
// =================================================================
__global__ __launch_bounds__(256) void aggregate_kernel(float* __restrict__ out)
{
    const int warp = threadIdx.x >> 5;
    const int lane = threadIdx.x & 31;
    const int n = blockIdx.x * 8 + warp;
    if (n >= N_NODES) return;

    const uint2* Qh2 = reinterpret_cast<const uint2*>(g_Qh);
    const uint4* KV4 = reinterpret_cast<const uint4*>(g_KVh);

    uint2 qr = Qh2[(size_t)n * 32 + lane];
    float2 q01 = __half22float2(*reinterpret_cast<const __half2*>(&qr.x));
    float2 q23 = __half22float2(*reinterpret_cast<const __half2*>(&qr.y));

    int i   = g_rowptr[n];
    const int end = g_rowptr[n + 1];

    float a0 = 0.f, a1 = 0.f, a2 = 0.f, a3 = 0.f, z = 0.f;

    uint4 kv = make_uint4(0u, 0u, 0u, 0u);
    if (i < end) {
        int s = g_srcsorted[i];
        kv = KV4[(size_t)s * 32 + lane];
    }

    while (i < end) {
        uint4 kvn = kv;
        int inext = i + 1;
        if (inext < end) {
            int s2 = g_srcsorted[inext];
            kvn = KV4[(size_t)s2 * 32 + lane];
        }

        float2 k01 = __half22float2(*reinterpret_cast<const __half2*>(&kv.x));
        float2 k23 = __half22float2(*reinterpret_cast<const __half2*>(&kv.y));

        float part = q01.x * k01.x + q01.y * k01.y + q23.x * k23.x + q23.y * k23.y;
        part += __shfl_xor_sync(0xFFFFFFFFu, part, 1);
        part += __shfl_xor_sync(0xFFFFFFFFu, part, 2);

        float sc = part * 0.25f;
        sc = fminf(fmaxf(sc, -5.0f), 5.0f);
        float w = __expf(sc);

        float2 v01 = __half22float2(*reinterpret_cast<const __half2*>(&kv.z));
        float2 v23 = __half22float2(*reinterpret_cast<const __half2*>(&kv.w));

        a0 = fmaf(w, v01.x, a0);
        a1 = fmaf(w, v01.y, a1);
        a2 = fmaf(w, v23.x, a2);
        a3 = fmaf(w, v23.y, a3);
        z += w;

        kv = kvn; i = inext;
    }

    float inv = 1.0f / z;
    float4 o = make_float4(a0 * inv, a1 * inv, a2 * inv, a3 * inv);
    *reinterpret_cast<float4*>(&out[(size_t)n * HD + lane * 4]) = o;
}

// =================================================================
extern "C" void kernel_launch(void* const* d_in, const int* in_sizes, int n_in,
                              void* d_out, int out_size)
{
    const float* state = (const float*)d_in[0];
    const int*   src   = (const int*)d_in[1];
    const int*   dst   = (const int*)d_in[2];
    const float* WQ    = (const float*)d_in[3];
    const float* bQ    = (const float*)d_in[4];
    const float* WK    = (const float*)d_in[5];
    const float* bK    = (const float*)d_in[6];
    const float* WV    = (const float*)d_in[7];
    const float* bV    = (const float*)d_in[8];
    float* out = (float*)d_out;

    const int n_edges = in_sizes[1];

    // second stream for CSR build, forked/joined with events so the
    // whole thing stays graph-capturable (capture follows the event deps).
    cudaStream_t s2;
    cudaStreamCreateWithFlags(&s2, cudaStreamNonBlocking);
    cudaEvent_t evFork, evJoin;
    cudaEventCreateWithFlags(&evFork, cudaEventDisableTiming);
    cudaEventCreateWithFlags(&evJoin, cudaEventDisableTiming);

    cudaEventRecord(evFork, 0);
    cudaStreamWaitEvent(s2, evFork, 0);

    // ---- CSR build on s2 (independent of GEMM) ----
    void* histAddr = nullptr;
    cudaGetSymbolAddress(&histAddr, g_hist);
    cudaMemsetAsync(histAddr, 0, N_NODES * sizeof(int), s2);
    hist_kernel<<<(n_edges + 255) / 256, 256, 0, s2>>>(dst, n_edges);
    scan_kernel<<<1, 1024, 0, s2>>>();
    scatter_kernel<<<(n_edges + 255) / 256, 256, 0, s2>>>(src, dst, n_edges);
    cudaEventRecord(evJoin, s2);

    // ---- QKV projections on default stream (overlaps CSR) ----
    dim3 ggrid((N_NODES + 127) / 128, 1, 3);
    qkv_gemm<<<ggrid, 256>>>(state, WQ, bQ, WK, bK, WV, bV);

    // ---- join, then fused gather/attention/aggregate/normalize ----
    cudaStreamWaitEvent(0, evJoin, 0);
    aggregate_kernel<<<(N_NODES + 7) / 8, 256>>>(out);
}

// round 7
// speedup vs baseline: 1.0237x; 1.0237x over previous
#include <cuda_runtime.h>
#include <cuda_fp16.h>
#include <mma.h>

using namespace nvcuda;

#define N_NODES  50000
#define IN_DIM   128
#define N_HEADS  8
#define OUT_DIM  16
#define HD       (N_HEADS * OUT_DIM)   // 128
#define MAX_EDGES 1600000

// -------- scratch (static device globals; allocation-free) --------
__device__ __align__(16) __half g_Qh [(size_t)N_NODES * HD];
// interleaved K|V: per node 32 groups x (4 K halves + 4 V halves) = 256 halves
__device__ __align__(16) __half g_KVh[(size_t)N_NODES * 2 * HD];
__device__ int g_hist[N_NODES];
__device__ int g_rowptr[N_NODES + 1];
__device__ int g_cursor[N_NODES];
__device__ int g_srcsorted[MAX_EDGES];

// =================================================================
// CSR build: histogram -> scan -> scatter (counting sort by dst)
// =================================================================
__global__ void hist_kernel(const int* __restrict__ dst, int n_edges)
{
    int e = blockIdx.x * blockDim.x + threadIdx.x;
    if (e < n_edges) atomicAdd(&g_hist[dst[e]], 1);
}

// single block, 1024 threads; 50000 entries, 49 per thread
__global__ __launch_bounds__(1024) void scan_kernel()
{
    __shared__ int part[1024];
    const int CHUNK = 49;
    int t = threadIdx.x;
    int begin = t * CHUNK;
    int end   = begin + CHUNK; if (end > N_NODES) end = N_NODES;
    if (begin > N_NODES) begin = N_NODES;

    int s = 0;
    for (int i = begin; i < end; i++) s += g_hist[i];
    part[t] = s;
    __syncthreads();

    for (int off = 1; off < 1024; off <<= 1) {
        int v = (t >= off) ? part[t - off] : 0;
        __syncthreads();
        part[t] += v;
        __syncthreads();
    }

    int base = (t == 0) ? 0 : part[t - 1];
    for (int i = begin; i < end; i++) {
        g_rowptr[i] = base;
        g_cursor[i] = base;
        base += g_hist[i];
    }
    if (t == 1023) g_rowptr[N_NODES] = part[1023];
}

__global__ void scatter_kernel(const int* __restrict__ src,
                               const int* __restrict__ dst, int n_edges)
{
    int e = blockIdx.x * blockDim.x + threadIdx.x;
    if (e < n_edges) {
        int d = dst[e];
        int pos = atomicAdd(&g_cursor[d], 1);
        g_srcsorted[pos] = src[e];
    }
}

// =================================================================
// QKV projection on tensor cores: tf32 wmma (m16n16k8), fp32 accum.
// BM=128, BN=128(=HD), BK=32, 256 threads (8 warps: 4 along M x 2
// along N; each warp owns 32x64 = 2x4 wmma tiles). Q -> g_Qh,
// K,V -> interleaved g_KVh, all fp16.
// =================================================================
__global__ __launch_bounds__(256) void qkv_gemm_tc(
    const float* __restrict__ state,
    const float* __restrict__ WQ, const float* __restrict__ bQ,
    const float* __restrict__ WK, const float* __restrict__ bK,
    const float* __restrict__ WV, const float* __restrict__ bV)
{
    const float* W;
    const float* b;
    if (blockIdx.z == 0)      { W = WQ; b = bQ; }
    else if (blockIdx.z == 1) { W = WK; b = bK; }
    else                      { W = WV; b = bV; }

    __shared__ __align__(16) float As[128][36];     // A[m][k], pad->no conflicts
    __shared__ __align__(16) float Bs[32][128];     // B[k][n]
    __shared__ __align__(16) float Stage[8][16 * 20]; // per-warp epilogue patch

    const int row0 = blockIdx.x * 128;
    const int tid  = threadIdx.x;
    const int wid  = tid >> 5;
    const int lane = tid & 31;
    const int warp_m = wid & 3;    // 32-row strip
    const int warp_n = wid >> 2;   // 64-col strip

    wmma::fragment<wmma::accumulator, 16, 16, 8, float> acc[2][4];
#pragma unroll
    for (int i = 0; i < 2; i++)
#pragma unroll
        for (int j = 0; j < 4; j++) wmma::fill_fragment(acc[i][j], 0.0f);

    for (int k0 = 0; k0 < IN_DIM; k0 += 32) {
        // ---- A chunk: 128 rows x 32 k ----
#pragma unroll
        for (int i = 0; i < 4; i++) {
            int idx = tid + i * 256;       // 0..1023 float4 slots
            int r   = idx >> 3;
            int kq  = idx & 7;
            int grow = row0 + r;
            float4 a = make_float4(0.f, 0.f, 0.f, 0.f);
            if (grow < N_NODES)
                a = *reinterpret_cast<const float4*>(&state[(size_t)grow * IN_DIM + k0 + kq * 4]);
            *reinterpret_cast<float4*>(&As[r][kq * 4]) = a;
        }
        // ---- B chunk: Bs[k][n] = W[(k0+k)*HD + n] ----
#pragma unroll
        for (int i = 0; i < 4; i++) {
            int idx = tid + i * 256;
            int k   = idx >> 5;
            int nq  = idx & 31;
            float4 wv = *reinterpret_cast<const float4*>(&W[(size_t)(k0 + k) * HD + nq * 4]);
            *reinterpret_cast<float4*>(&Bs[k][nq * 4]) = wv;
        }
        __syncthreads();

#pragma unroll
        for (int ks = 0; ks < 4; ks++) {   // k-steps of 8
            wmma::fragment<wmma::matrix_a, 16, 16, 8, wmma::precision::tf32, wmma::row_major> af[2];
            wmma::fragment<wmma::matrix_b, 16, 16, 8, wmma::precision::tf32, wmma::row_major> bf[4];
#pragma unroll
            for (int i = 0; i < 2; i++) {
                wmma::load_matrix_sync(af[i], &As[warp_m * 32 + i * 16][ks * 8], 36);
#pragma unroll
                for (int t = 0; t < af[i].num_elements; t++)
                    af[i].x[t] = wmma::__float_to_tf32(af[i].x[t]);
            }
#pragma unroll
            for (int j = 0; j < 4; j++) {
                wmma::load_matrix_sync(bf[j], &Bs[ks * 8][warp_n * 64 + j * 16], 128);
#pragma unroll
                for (int t = 0; t < bf[j].num_elements; t++)
                    bf[j].x[t] = wmma::__float_to_tf32(bf[j].x[t]);
            }
#pragma unroll
            for (int i = 0; i < 2; i++)
#pragma unroll
                for (int j = 0; j < 4; j++)
                    wmma::mma_sync(acc[i][j], af[i], bf[j], acc[i][j]);
        }
        __syncthreads();
    }

    // ---- epilogue: per-warp 16x16 staging, bias, fp16, interleaved store ----
    float* patch = &Stage[wid][0];
    const int r  = lane >> 1;
    const int c0 = (lane & 1) * 8;

#pragma unroll
    for (int i = 0; i < 2; i++) {
#pragma unroll
        for (int j = 0; j < 4; j++) {
            wmma::store_matrix_sync(patch, acc[i][j], 20, wmma::mem_row_major);
            __syncwarp();

            int grow = row0 + warp_m * 32 + i * 16 + r;
            int gcol = warp_n * 64 + j * 16 + c0;   // multiple of 8
            if (grow < N_NODES) {
                float o[8];
#pragma unroll
                for (int t = 0; t < 8; t++)
                    o[t] = patch[r * 20 + c0 + t] + b[gcol + t];
                __half2 h[4];
#pragma unroll
                for (int t = 0; t < 4; t++)
                    h[t] = __floats2half2_rn(o[2 * t], o[2 * t + 1]);

                if (blockIdx.z == 0) {
                    *reinterpret_cast<uint4*>(&g_Qh[(size_t)grow * HD + gcol]) =
                        *reinterpret_cast<const uint4*>(h);
                } else {
                    __half* rowp = &g_KVh[(size_t)grow * 2 * HD];
                    int off = (blockIdx.z == 1) ? 0 : 4;
                    int g0  = gcol >> 2;            // first of two groups
                    uint2 lo = make_uint2(*reinterpret_cast<unsigned*>(&h[0]),
                                          *reinterpret_cast<unsigned*>(&h[1]));
                    uint2 hi = make_uint2(*reinterpret_cast<unsigned*>(&h[2]),
                                          *reinterpret_cast<unsigned*>(&h[3]));
                    *reinterpret_cast<uint2*>(&rowp[g0 * 8 + off])       = lo;
                    *reinterpret_cast<uint2*>(&rowp[(g0 + 1) * 8 + off]) = hi;
                }
            }
            __syncwarp();
        }
    }
}

// =================================================================
// Aggregate: warp per dst node. lane l owns dims [4l,4l+4);
// head h = l>>2. Q register-resident; indices batched 32-at-a-time
// and broadcast via shfl; one uint4 KV gather per edge, depth-2
// pipelined. Register accumulation, fused normalize.
// =================================================================
__global__ __launch_bounds__(256) void aggregate_kernel(float* __restrict__ out)
{
    const int warp = threadIdx.x >> 5;
    const int lane = threadIdx.x & 31;
    const int n = blockIdx.x * 8 + warp;
    if (n >= N_NODES) return;

    const uint2* Qh2 = reinterpret_cast<const uint2*>(g_Qh);
    const uint4* KV4 = reinterpret_cast<const uint4*>(g_KVh);

    uint2 qr = Qh2[(size_t)n * 32 + lane];
    float2 q01 = __half22float2(*reinterpret_cast<const __half2*>(&qr.x));
    float2 q23 = __half22float2(*reinterpret_cast<const __half2*>(&qr.y));

    const int beg = g_rowptr[n];
    const int end = g_rowptr[n + 1];

    float a0 = 0.f, a1 = 0.f, a2 = 0.f, a3 = 0.f, z = 0.f;
    const unsigned mask = 0xFFFFFFFFu;

    for (int base = beg; base < end; base += 32) {
        int cnt = end - base; if (cnt > 32) cnt = 32;
        int my = 0;
        if (base + lane < end) my = g_srcsorted[base + lane];

        int s0 = __shfl_sync(mask, my, 0);
        uint4 kv = KV4[(size_t)s0 * 32 + lane];

        for (int j = 0; j < cnt; j++) {
            uint4 nxt = kv;
            if (j + 1 < cnt) {
                int s1 = __shfl_sync(mask, my, j + 1);
                nxt = KV4[(size_t)s1 * 32 + lane];
            }

            float2 k01 = __half22float2(*reinterpret_cast<const __half2*>(&kv.x));
            float2 k23 = __half22float2(*reinterpret_cast<const __half2*>(&kv.y));

            float part = q01.x * k01.x + q01.y * k01.y + q23.x * k23.x + q23.y * k23.y;
            part += __shfl_xor_sync(mask, part, 1);
            part += __shfl_xor_sync(mask, part, 2);

            float sc = part * 0.25f;
            sc = fminf(fmaxf(sc, -5.0f), 5.0f);
            float w = __expf(sc);

            float2 v01 = __half22float2(*reinterpret_cast<const __half2*>(&kv.z));
            float2 v23 = __half22float2(*reinterpret_cast<const __half2*>(&kv.w));

            a0 = fmaf(w, v01.x, a0);
            a1 = fmaf(w, v01.y, a1);
            a2 = fmaf(w, v23.x, a2);
            a3 = fmaf(w, v23.y, a3);
            z += w;

            kv = nxt;
        }
    }

    float inv = 1.0f / z;
    float4 o = make_float4(a0 * inv, a1 * inv, a2 * inv, a3 * inv);
    *reinterpret_cast<float4*>(&out[(size_t)n * HD + lane * 4]) = o;
}

// =================================================================
extern "C" void kernel_launch(void* const* d_in, const int* in_sizes, int n_in,
                              void* d_out, int out_size)
{
    const float* state = (const float*)d_in[0];
    const int*   src   = (const int*)d_in[1];
    const int*   dst   = (const int*)d_in[2];
    const float* WQ    = (const float*)d_in[3];
    const float* bQ    = (const float*)d_in[4];
    const float* WK    = (const float*)d_in[5];
    const float* bK    = (const float*)d_in[6];
    const float* WV    = (const float*)d_in[7];
    const float* bV    = (const float*)d_in[8];
    float* out = (float*)d_out;

    const int n_edges = in_sizes[1];

    // fork a second stream for the CSR build (independent of the GEMM);
    // event deps keep it graph-capturable.
    cudaStream_t s2;
    cudaStreamCreateWithFlags(&s2, cudaStreamNonBlocking);
    cudaEvent_t evFork, evJoin;
    cudaEventCreateWithFlags(&evFork, cudaEventDisableTiming);
    cudaEventCreateWithFlags(&evJoin, cudaEventDisableTiming);

    cudaEventRecord(evFork, 0);
    cudaStreamWaitEvent(s2, evFork, 0);

    // ---- CSR build on s2 ----
    void* histAddr = nullptr;
    cudaGetSymbolAddress(&histAddr, g_hist);
    cudaMemsetAsync(histAddr, 0, N_NODES * sizeof(int), s2);
    hist_kernel<<<(n_edges + 255) / 256, 256, 0, s2>>>(dst, n_edges);
    scan_kernel<<<1, 1024, 0, s2>>>();
    scatter_kernel<<<(n_edges + 255) / 256, 256, 0, s2>>>(src, dst, n_edges);
    cudaEventRecord(evJoin, s2);

    // ---- QKV projections on default stream (tensor cores) ----
    dim3 ggrid((N_NODES + 127) / 128, 1, 3);
    qkv_gemm_tc<<<ggrid, 256>>>(state, WQ, bQ, WK, bK, WV, bV);

    // ---- join, then fused gather/attention/aggregate/normalize ----
    cudaStreamWaitEvent(0, evJoin, 0);
    aggregate_kernel<<<(N_NODES + 7) / 8, 256>>>(out);
}